// round 8
// baseline (speedup 1.0000x reference)
#include <cuda_runtime.h>
#include <cuda_bf16.h>
#include <cstdint>

#define NN   128            // state size
#define NB   2              // batch
#define LL   2048           // sequence length
#define TC   16             // chunk length
#define KC   (LL / TC)      // 128 chunks per batch
#define NG   8              // chunks per group
#define GG   (KC / NG)      // 16 groups per batch

// ---------------- device scratch ----------------
__device__ float  g_AdT[NN * NN];     // AdT[k*128+j] = Ad[j][k]
__device__ float  g_Bd[NN];
__device__ float  g_PT[NN * NN];      // P = Ad^16, transposed layout
__device__ float  g_QT[NN * NN];      // Q = P^8 = Ad^128, transposed layout
__device__ float  g_locend[NB * KC * NN];   // chunk-local end states
__device__ float  g_gle[NB * GG * NN];      // group-local end states
__device__ float  g_gentry[NB * GG * NN];   // group entry states
__device__ float  g_states[NB * LL * NN];   // all true states c_t (2 MB)

// ---------------- 1) discretize (A in shared; fp64 forward substitution) ------
// Solve (I - 0.5 A) X = (I + 0.5 A) columnwise and (I - 0.5 A) Bd = B.
// A lower triangular. Block c: column c of Ad (c<128) or Bd (c==128).
// A loaded to shared with 129-stride padding -> conflict-free column reads.
__global__ void __launch_bounds__(NN) k_disc(const float* __restrict__ A,
                                             const float* __restrict__ B) {
    __shared__ float  sA[NN * 129];
    __shared__ double dinv[NN];
    __shared__ double xsh[2];
    int c = blockIdx.x, i = threadIdx.x;

    for (int idx = i; idx < NN * NN; idx += NN) {
        int r = idx >> 7, cc = idx & 127;
        sA[r * 129 + cc] = A[idx];
    }
    __syncthreads();

    dinv[i] = 1.0 / (1.0 - 0.5 * (double)sA[i * 130]);   // A[i][i]

    double ri;
    if (c < NN) ri = (i == c ? 1.0 : 0.0) + 0.5 * (double)sA[i * 129 + c];
    else        ri = (double)B[i];
    __syncthreads();

    for (int j = 0; j < NN; j++) {
        if (i == j) xsh[j & 1] = ri * dinv[j];
        __syncthreads();
        double x = xsh[j & 1];
        if (i > j)       ri = fma(0.5 * (double)sA[i * 129 + j], x, ri);
        else if (i == j) ri = x;
        // next write goes to the other xsh buffer; one bar per step suffices
    }
    if (c < NN) g_AdT[c * NN + i] = (float)ri;   // Ad[i][c] at AdT[c*128+i]
    else        g_Bd[i] = (float)ri;
}

// ---------------- canonical serial-matvec pieces (128 thr, 1 bar/step) --------
// Thread j holds matrix row j in registers (from transposed layout M[k*128+j]).
__device__ __forceinline__ void load_row(float* ad, const float* __restrict__ M,
                                         int j) {
#pragma unroll
    for (int k = 0; k < NN; k++) ad[k] = M[k * NN + j];
}

__device__ __forceinline__ float dot128(const float* __restrict__ ad,
                                        const float* __restrict__ csh) {
    const float4* c4 = (const float4*)csh;
    float a0 = 0.f, a1 = 0.f, a2 = 0.f, a3 = 0.f;
#pragma unroll
    for (int k4 = 0; k4 < 32; k4++) {
        float4 cv = c4[k4];
        a0 = fmaf(ad[4 * k4 + 0], cv.x, a0);
        a1 = fmaf(ad[4 * k4 + 1], cv.y, a1);
        a2 = fmaf(ad[4 * k4 + 2], cv.z, a2);
        a3 = fmaf(ad[4 * k4 + 3], cv.w, a3);
    }
    return (a0 + a1) + (a2 + a3);
}

// matvec step with the matrix row read from global (L2-resident), coalesced
__device__ __forceinline__ float dot128_g(const float* __restrict__ M,
                                          const float* __restrict__ csh, int j) {
    float a0 = 0.f, a1 = 0.f, a2 = 0.f, a3 = 0.f;
#pragma unroll 8
    for (int k = 0; k < NN; k += 4) {
        a0 = fmaf(M[(k + 0) * NN + j], csh[k + 0], a0);
        a1 = fmaf(M[(k + 1) * NN + j], csh[k + 1], a1);
        a2 = fmaf(M[(k + 2) * NN + j], csh[k + 2], a2);
        a3 = fmaf(M[(k + 3) * NN + j], csh[k + 3], a3);
    }
    return (a0 + a1) + (a2 + a3);
}

// ---------------- 2) chunk locals (256 blk) + P=Ad^16 columns (128 blk) -------
__global__ void __launch_bounds__(NN) k_chain(const float* __restrict__ f) {
    __shared__ float cur[2][NN];
    __shared__ float fsh[TC];
    int j = threadIdx.x;
    float ad[NN]; load_row(ad, g_AdT, j);

    int blk = blockIdx.x;
    if (blk < NB * KC) {                    // local scan from zero
        int b = blk >> 7, ch = blk & (KC - 1);
        float bd = g_Bd[j];
        if (j < TC) fsh[j] = f[b * LL + ch * TC + j];
        cur[0][j] = 0.f;
        __syncthreads();
        float nc = 0.f;
        for (int s = 0; s < TC; s++) {
            float d = dot128(ad, cur[s & 1]);
            nc = fmaf(bd, fsh[s], d);
            cur[(s + 1) & 1][j] = nc;
            __syncthreads();
        }
        g_locend[(b * KC + ch) * NN + j] = nc;
    } else {                                 // column j0 of P = Ad^16
        int j0 = blk - NB * KC;
        cur[0][j] = (j == j0) ? 1.f : 0.f;
        __syncthreads();
        float nc = 0.f;
        for (int s = 0; s < TC; s++) {
            nc = dot128(ad, cur[s & 1]);
            cur[(s + 1) & 1][j] = nc;
            __syncthreads();
        }
        g_PT[j0 * NN + j] = nc;              // P[j][j0]
    }
}

// ---------------- 3) Q=P^8 columns (128 blk) + group-local scans (32 blk) -----
__global__ void __launch_bounds__(NN) k_powgroup() {
    __shared__ float cur[2][NN];
    __shared__ float add[NG][NN];
    int j = threadIdx.x;
    float ap[NN]; load_row(ap, g_PT, j);

    int blk = blockIdx.x;
    if (blk < NN) {                          // column j0 of Q = P^8
        int j0 = blk;
        cur[0][j] = (j == j0) ? 1.f : 0.f;
        __syncthreads();
        float nc = 0.f;
        for (int s = 0; s < NG; s++) {
            nc = dot128(ap, cur[s & 1]);
            cur[(s + 1) & 1][j] = nc;
            __syncthreads();
        }
        g_QT[j0 * NN + j] = nc;
    } else {                                 // group-local: z <- P z + locend
        int gb = blk - NN;                   // 0..31
        int b = gb >> 4, g = gb & (GG - 1);
        for (int s = 0; s < NG; s++)
            add[s][j] = g_locend[(b * KC + g * NG + s) * NN + j];
        cur[0][j] = 0.f;
        __syncthreads();
        float nc = 0.f;
        for (int s = 0; s < NG; s++) {
            float d = dot128(ap, cur[s & 1]);
            nc = d + add[s][j];
            cur[(s + 1) & 1][j] = nc;
            __syncthreads();
        }
        g_gle[(b * GG + g) * NN + j] = nc;
    }
}

// ---------------- 4) group-entry scan with Q (2 blocks, depth 16) -------------
__global__ void __launch_bounds__(NN) k_carryB(float* __restrict__ cfin) {
    __shared__ float cur[2][NN];
    __shared__ float add[GG][NN];
    int j = threadIdx.x, b = blockIdx.x;
    float aq[NN]; load_row(aq, g_QT, j);

    for (int g = 0; g < GG; g++)
        add[g][j] = g_gle[(b * GG + g) * NN + j];
    cur[0][j] = 0.f;
    g_gentry[(b * GG + 0) * NN + j] = 0.f;
    __syncthreads();

    for (int g = 1; g <= GG; g++) {
        float d = dot128(aq, cur[(g - 1) & 1]);
        float nc = d + add[g - 1][j];
        cur[g & 1][j] = nc;
        if (g < GG)   g_gentry[(b * GG + g) * NN + j] = nc;
        else if (cfin) cfin[b * NN + j] = nc;     // c_final
        __syncthreads();
    }
}

// ---------------- 5) states: fold chunk-carry replay + main recurrence --------
// Block (b, ch=g*8+c): prelude advances gentry(g) by c P-steps (P rows read from
// L2), then runs the 16 Ad-steps and stores states.
__global__ void __launch_bounds__(NN) k_states(const float* __restrict__ f) {
    __shared__ float cur[2][NN];
    __shared__ float fsh[TC];
    int j = threadIdx.x;
    int ch = blockIdx.x, b = blockIdx.y;
    int g = ch >> 3, c = ch & (NG - 1);

    float ad[NN]; load_row(ad, g_AdT, j);
    float bd = g_Bd[j];

    if (j < TC) fsh[j] = f[b * LL + ch * TC + j];
    cur[0][j] = g_gentry[(b * GG + g) * NN + j];
    __syncthreads();

    // prelude: carry(ch) = P^c * gentry + local scan of preceding chunks
    int buf = 0;
    for (int s = 0; s < c; s++) {
        float d = dot128_g(g_PT, cur[buf], j);
        float nc = d + g_locend[(b * KC + g * NG + s) * NN + j];
        buf ^= 1;
        cur[buf][j] = nc;
        __syncthreads();
    }

    float* sp = g_states + ((size_t)(b * LL + ch * TC)) * NN;
    for (int s = 0; s < TC; s++) {
        float d = dot128(ad, cur[buf]);
        float nc = fmaf(bd, fsh[s], d);
        buf ^= 1;
        cur[buf][j] = nc;
        sp[(size_t)s * NN + j] = nc;        // coalesced, off critical path
        __syncthreads();
    }
}

// ---------------- 6) streaming expansion: y[b,t,n,k] = C[n]*c_t[k] + D*f_t ----
__global__ void __launch_bounds__(256) k_expand(const float* __restrict__ f,
                                                const float* __restrict__ C,
                                                const float* __restrict__ D,
                                                float* __restrict__ y) {
    __shared__ float cs[NN];
    __shared__ float Csh[NN];
    int tid = threadIdx.x;
    int t = blockIdx.x, b = blockIdx.y;

    if (tid < NN) {
        cs[tid]  = g_states[((size_t)(b * LL + t)) * NN + tid];
        Csh[tid] = C[tid];
    }
    float df = D[0] * f[b * LL + t];
    __syncthreads();

    float4* out = (float4*)(y + ((size_t)(b * LL + t)) * (NN * NN));
    float4 cv = ((const float4*)cs)[tid & 31];
    int n0 = tid >> 5;
#pragma unroll
    for (int it = 0; it < 16; it++) {
        float cn = Csh[n0 + 8 * it];
        float4 o;
        o.x = fmaf(cn, cv.x, df);
        o.y = fmaf(cn, cv.y, df);
        o.z = fmaf(cn, cv.z, df);
        o.w = fmaf(cn, cv.w, df);
        out[tid + 256 * it] = o;
    }
}

// ---------------- launcher ----------------------------------------------------
extern "C" void kernel_launch(void* const* d_in, const int* in_sizes, int n_in,
                              void* d_out, int out_size) {
    const float* f = (const float*)d_in[0];
    const float* A = (const float*)d_in[1];
    const float* B = (const float*)d_in[2];
    const float* C = (const float*)d_in[3];
    const float* D = (const float*)d_in[4];

    const long long Y_ELEMS = (long long)NB * LL * NN * NN;   // 67,108,864
    long long off = (long long)out_size - Y_ELEMS;
    if (off < 0) off = 0;
    float* y    = (float*)d_out + off;
    float* cfin = (off >= NB * NN) ? (float*)d_out : nullptr;

    k_disc<<<NN + 1, NN>>>(A, B);
    k_chain<<<NB * KC + NN, NN>>>(f);        // 384 blocks
    k_powgroup<<<NN + NB * GG, NN>>>();      // 160 blocks
    k_carryB<<<NB, NN>>>(cfin);
    k_states<<<dim3(KC, NB), NN>>>(f);
    k_expand<<<dim3(LL, NB), 256>>>(f, C, D, y);
}

// round 9
// speedup vs baseline: 1.0764x; 1.0764x over previous
#include <cuda_runtime.h>
#include <cuda_bf16.h>
#include <cstdint>

#define NN   128            // state size
#define NB   2              // batch
#define LL   2048           // sequence length
#define TC   16             // chunk length
#define KC   (LL / TC)      // 128 chunks per batch
#define NG   8              // chunks per group
#define GG   (KC / NG)      // 16 groups per batch

// ---------------- device scratch ----------------
__device__ float  g_AdT[NN * NN];     // AdT[k*128+j] = Ad[j][k]
__device__ float  g_Bd[NN];
__device__ float  g_PT[NN * NN];      // P = Ad^16, transposed layout
__device__ float  g_QT[NN * NN];      // Q = P^8 = Ad^128, transposed layout
__device__ float  g_locend[NB * KC * NN];   // chunk-local end states
__device__ float  g_gle[NB * GG * NN];      // group-local end states
__device__ float  g_gentry[NB * GG * NN];   // group entry states
__device__ float  g_carry[NB * KC * NN];    // chunk entry states
__device__ float  g_states[NB * LL * NN];   // all true states c_t (2 MB)

// ---------------- 1) discretize: single-warp fp32 forward substitution --------
// Solve (I - 0.5 A) X = (I + 0.5 A) columnwise and (I - 0.5 A) Bd = B.
// A lower triangular. Block c: column c of Ad (c<128) or Bd (c==128).
// All 128 threads transpose A into padded shared; warp 0 solves with 4 rows
// per thread, x_j broadcast via shfl (no block barrier on the critical path),
// Kahan-compensated accumulation for fp32 safety.
#define PAD 132
__global__ void __launch_bounds__(NN) k_disc(const float* __restrict__ A,
                                             const float* __restrict__ B) {
    __shared__ float sAT[NN * PAD];   // sAT[j*PAD + i] = A[i][j]
    int c = blockIdx.x, tid = threadIdx.x;

    for (int idx = tid; idx < NN * NN; idx += NN) {
        int i = idx >> 7, j = idx & 127;
        sAT[j * PAD + i] = A[idx];
    }
    __syncthreads();

    if (tid < 32) {
        int t = tid;
        float r[4], comp[4] = {0.f, 0.f, 0.f, 0.f}, dinv[4];
#pragma unroll
        for (int m = 0; m < 4; m++) {
            int i = 4 * t + m;
            dinv[m] = 1.0f / (1.0f - 0.5f * sAT[i * PAD + i]);
        }
        if (c < NN) {
#pragma unroll
            for (int m = 0; m < 4; m++) {
                int i = 4 * t + m;
                r[m] = (i == c ? 1.0f : 0.0f) + 0.5f * sAT[c * PAD + i];
            }
        } else {
#pragma unroll
            for (int m = 0; m < 4; m++) r[m] = B[4 * t + m];
        }

        float4 col = *(const float4*)&sAT[0 * PAD + 4 * t];   // 16B aligned (PAD=132)
        for (int j = 0; j < NN; j++) {
            float4 nxt = col;
            if (j + 1 < NN) nxt = *(const float4*)&sAT[(j + 1) * PAD + 4 * t];
            int owner = j >> 2, m0 = j & 3;
            float x = __shfl_sync(0xffffffffu, r[m0] * dinv[m0], owner);
            float av[4] = {col.x, col.y, col.z, col.w};
#pragma unroll
            for (int m = 0; m < 4; m++) {
                int i = 4 * t + m;
                if (i > j) {                       // Kahan: r += 0.5*a*x
                    float yv = fmaf(0.5f * av[m], x, -comp[m]);
                    float sv = r[m] + yv;
                    comp[m] = (sv - r[m]) - yv;
                    r[m] = sv;
                } else if (i == j) {
                    r[m] = x;
                }
            }
            col = nxt;
        }
        if (c < NN) {
#pragma unroll
            for (int m = 0; m < 4; m++) g_AdT[c * NN + 4 * t + m] = r[m];
        } else {
#pragma unroll
            for (int m = 0; m < 4; m++) g_Bd[4 * t + m] = r[m];
        }
    }
}

// ---------------- canonical serial-matvec pieces (128 thr, 1 bar/step) --------
// Thread j holds matrix row j in registers (from transposed layout M[k*128+j]).
__device__ __forceinline__ void load_row(float* ad, const float* __restrict__ M,
                                         int j) {
#pragma unroll
    for (int k = 0; k < NN; k++) ad[k] = M[k * NN + j];
}

__device__ __forceinline__ float dot128(const float* __restrict__ ad,
                                        const float* __restrict__ csh) {
    const float4* c4 = (const float4*)csh;
    float a0 = 0.f, a1 = 0.f, a2 = 0.f, a3 = 0.f;
#pragma unroll
    for (int k4 = 0; k4 < 32; k4++) {
        float4 cv = c4[k4];
        a0 = fmaf(ad[4 * k4 + 0], cv.x, a0);
        a1 = fmaf(ad[4 * k4 + 1], cv.y, a1);
        a2 = fmaf(ad[4 * k4 + 2], cv.z, a2);
        a3 = fmaf(ad[4 * k4 + 3], cv.w, a3);
    }
    return (a0 + a1) + (a2 + a3);
}

// ---------------- 2) chunk locals (256 blk) + P=Ad^16 columns (128 blk) -------
__global__ void __launch_bounds__(NN) k_chain(const float* __restrict__ f) {
    __shared__ float cur[2][NN];
    __shared__ float fsh[TC];
    int j = threadIdx.x;
    float ad[NN]; load_row(ad, g_AdT, j);

    int blk = blockIdx.x;
    if (blk < NB * KC) {                    // local scan from zero
        int b = blk >> 7, ch = blk & (KC - 1);
        float bd = g_Bd[j];
        if (j < TC) fsh[j] = f[b * LL + ch * TC + j];
        cur[0][j] = 0.f;
        __syncthreads();
        float nc = 0.f;
        for (int s = 0; s < TC; s++) {
            float d = dot128(ad, cur[s & 1]);
            nc = fmaf(bd, fsh[s], d);
            cur[(s + 1) & 1][j] = nc;
            __syncthreads();
        }
        g_locend[(b * KC + ch) * NN + j] = nc;
    } else {                                 // column j0 of P = Ad^16
        int j0 = blk - NB * KC;
        cur[0][j] = (j == j0) ? 1.f : 0.f;
        __syncthreads();
        float nc = 0.f;
        for (int s = 0; s < TC; s++) {
            nc = dot128(ad, cur[s & 1]);
            cur[(s + 1) & 1][j] = nc;
            __syncthreads();
        }
        g_PT[j0 * NN + j] = nc;              // P[j][j0]
    }
}

// ---------------- 3) Q=P^8 columns (128 blk) + group-local scans (32 blk) -----
__global__ void __launch_bounds__(NN) k_powgroup() {
    __shared__ float cur[2][NN];
    __shared__ float add[NG][NN];
    int j = threadIdx.x;
    float ap[NN]; load_row(ap, g_PT, j);

    int blk = blockIdx.x;
    if (blk < NN) {                          // column j0 of Q = P^8
        int j0 = blk;
        cur[0][j] = (j == j0) ? 1.f : 0.f;
        __syncthreads();
        float nc = 0.f;
        for (int s = 0; s < NG; s++) {
            nc = dot128(ap, cur[s & 1]);
            cur[(s + 1) & 1][j] = nc;
            __syncthreads();
        }
        g_QT[j0 * NN + j] = nc;
    } else {                                 // group-local: z <- P z + locend
        int gb = blk - NN;                   // 0..31
        int b = gb >> 4, g = gb & (GG - 1);
        for (int s = 0; s < NG; s++)
            add[s][j] = g_locend[(b * KC + g * NG + s) * NN + j];
        cur[0][j] = 0.f;
        __syncthreads();
        float nc = 0.f;
        for (int s = 0; s < NG; s++) {
            float d = dot128(ap, cur[s & 1]);
            nc = d + add[s][j];
            cur[(s + 1) & 1][j] = nc;
            __syncthreads();
        }
        g_gle[(b * GG + g) * NN + j] = nc;
    }
}

// ---------------- 4) group-entry scan with Q (2 blocks, depth 16) -------------
__global__ void __launch_bounds__(NN) k_carryB(float* __restrict__ cfin) {
    __shared__ float cur[2][NN];
    __shared__ float add[GG][NN];
    int j = threadIdx.x, b = blockIdx.x;
    float aq[NN]; load_row(aq, g_QT, j);

    for (int g = 0; g < GG; g++)
        add[g][j] = g_gle[(b * GG + g) * NN + j];
    cur[0][j] = 0.f;
    g_gentry[(b * GG + 0) * NN + j] = 0.f;
    __syncthreads();

    for (int g = 1; g <= GG; g++) {
        float d = dot128(aq, cur[(g - 1) & 1]);
        float nc = d + add[g - 1][j];
        cur[g & 1][j] = nc;
        if (g < GG)   g_gentry[(b * GG + g) * NN + j] = nc;
        else if (cfin) cfin[b * NN + j] = nc;     // c_final
        __syncthreads();
    }
}

// ---------------- 5) chunk carries within each group (32 blocks, depth 7) -----
__global__ void __launch_bounds__(NN) k_carryC() {
    __shared__ float cur[2][NN];
    __shared__ float add[NG][NN];
    int j = threadIdx.x;
    int b = blockIdx.x >> 4, g = blockIdx.x & (GG - 1);
    float ap[NN]; load_row(ap, g_PT, j);

    for (int s = 0; s < NG - 1; s++)
        add[s][j] = g_locend[(b * KC + g * NG + s) * NN + j];
    float e = g_gentry[(b * GG + g) * NN + j];
    cur[0][j] = e;
    g_carry[(b * KC + g * NG) * NN + j] = e;
    __syncthreads();

    for (int c = 1; c < NG; c++) {
        float d = dot128(ap, cur[(c - 1) & 1]);
        float nc = d + add[c - 1][j];
        cur[c & 1][j] = nc;
        g_carry[(b * KC + g * NG + c) * NN + j] = nc;
        __syncthreads();
    }
}

// ---------------- 6) replay recurrence with true carry, store states ----------
__global__ void __launch_bounds__(NN) k_states(const float* __restrict__ f) {
    __shared__ float cur[2][NN];
    __shared__ float fsh[TC];
    int j = threadIdx.x;
    int ch = blockIdx.x, b = blockIdx.y;
    float ad[NN]; load_row(ad, g_AdT, j);
    float bd = g_Bd[j];

    if (j < TC) fsh[j] = f[b * LL + ch * TC + j];
    cur[0][j] = g_carry[(b * KC + ch) * NN + j];
    float* sp = g_states + ((size_t)(b * LL + ch * TC)) * NN;
    __syncthreads();

    for (int s = 0; s < TC; s++) {
        float d = dot128(ad, cur[s & 1]);
        float nc = fmaf(bd, fsh[s], d);
        cur[(s + 1) & 1][j] = nc;
        sp[(size_t)s * NN + j] = nc;        // coalesced, off critical path
        __syncthreads();
    }
}

// ---------------- 7) streaming expansion: y[b,t,n,k] = C[n]*c_t[k] + D*f_t ----
__global__ void __launch_bounds__(256) k_expand(const float* __restrict__ f,
                                                const float* __restrict__ C,
                                                const float* __restrict__ D,
                                                float* __restrict__ y) {
    __shared__ float cs[NN];
    __shared__ float Csh[NN];
    int tid = threadIdx.x;
    int t = blockIdx.x, b = blockIdx.y;

    if (tid < NN) {
        cs[tid]  = g_states[((size_t)(b * LL + t)) * NN + tid];
        Csh[tid] = C[tid];
    }
    float df = D[0] * f[b * LL + t];
    __syncthreads();

    float4* out = (float4*)(y + ((size_t)(b * LL + t)) * (NN * NN));
    float4 cv = ((const float4*)cs)[tid & 31];
    int n0 = tid >> 5;
#pragma unroll
    for (int it = 0; it < 16; it++) {
        float cn = Csh[n0 + 8 * it];
        float4 o;
        o.x = fmaf(cn, cv.x, df);
        o.y = fmaf(cn, cv.y, df);
        o.z = fmaf(cn, cv.z, df);
        o.w = fmaf(cn, cv.w, df);
        out[tid + 256 * it] = o;
    }
}

// ---------------- launcher ----------------------------------------------------
extern "C" void kernel_launch(void* const* d_in, const int* in_sizes, int n_in,
                              void* d_out, int out_size) {
    const float* f = (const float*)d_in[0];
    const float* A = (const float*)d_in[1];
    const float* B = (const float*)d_in[2];
    const float* C = (const float*)d_in[3];
    const float* D = (const float*)d_in[4];

    const long long Y_ELEMS = (long long)NB * LL * NN * NN;   // 67,108,864
    long long off = (long long)out_size - Y_ELEMS;
    if (off < 0) off = 0;
    float* y    = (float*)d_out + off;
    float* cfin = (off >= NB * NN) ? (float*)d_out : nullptr;

    k_disc<<<NN + 1, NN>>>(A, B);
    k_chain<<<NB * KC + NN, NN>>>(f);        // 384 blocks
    k_powgroup<<<NN + NB * GG, NN>>>();      // 160 blocks
    k_carryB<<<NB, NN>>>(cfin);
    k_carryC<<<NB * GG, NN>>>();             // 32 blocks
    k_states<<<dim3(KC, NB), NN>>>(f);
    k_expand<<<dim3(LL, NB), 256>>>(f, C, D, y);
}

// round 12
// speedup vs baseline: 1.1574x; 1.0753x over previous
#include <cuda_runtime.h>
#include <cuda_bf16.h>
#include <cstdint>

#define NN   128            // state size
#define NB   2              // batch
#define LL   2048           // sequence length
#define TC   16             // chunk length
#define KC   (LL / TC)      // 128 chunks per batch
#define NG   8              // chunks per group
#define GG   (KC / NG)      // 16 groups per batch

// ---------------- device scratch ----------------
__device__ double g_ATd[NN * NN];     // A transposed, fp64
__device__ float  g_AdT[NN * NN];     // AdT[k*128+j] = Ad[j][k]
__device__ float  g_Bd[NN];
__device__ float  g_PT[NN * NN];      // P = Ad^16, transposed layout
__device__ float  g_QT[NN * NN];      // Q = P^8 = Ad^128, transposed layout
__device__ float  g_locend[NB * KC * NN];   // chunk-local end states
__device__ float  g_gle[NB * GG * NN];      // group-local end states
__device__ float  g_carry[NB * KC * NN];    // chunk entry states

// ---------------- 1) transpose A to fp64 (R5-proven) ----------------
__global__ void k_transpose(const float* __restrict__ A) {
    __shared__ float tile[32][33];
    int bx = blockIdx.x * 32, by = blockIdx.y * 32;
    int x = bx + threadIdx.x;
    for (int r = threadIdx.y; r < 32; r += 8)
        tile[r][threadIdx.x] = A[(by + r) * NN + x];
    __syncthreads();
    int xo = by + threadIdx.x;
    for (int r = threadIdx.y; r < 32; r += 8)
        g_ATd[(bx + r) * NN + xo] = (double)tile[threadIdx.x][r];
}

// ---------------- 2) discretize (R5-proven fp64 forward substitution) ---------
__global__ void __launch_bounds__(NN) k_disc(const float* __restrict__ B) {
    __shared__ double dinv[NN];
    __shared__ double xsh[2];
    int c = blockIdx.x, i = threadIdx.x;

    dinv[i] = 1.0 / (1.0 - 0.5 * g_ATd[i * NN + i]);

    double ri;
    if (c < NN) ri = (i == c ? 1.0 : 0.0) + 0.5 * g_ATd[c * NN + i];
    else        ri = (double)B[i];

    double a_next = 0.5 * g_ATd[0 * NN + i];
    __syncthreads();

    for (int j = 0; j < NN; j++) {
        double aj = a_next;
        if (j + 1 < NN) a_next = 0.5 * g_ATd[(j + 1) * NN + i];
        if (i == j) xsh[j & 1] = ri * dinv[j];
        __syncthreads();
        double x = xsh[j & 1];
        if (i > j)       ri = fma(aj, x, ri);
        else if (i == j) ri = x;
    }
    if (c < NN) g_AdT[c * NN + i] = (float)ri;   // Ad[i][c] at AdT[c*128+i]
    else        g_Bd[i] = (float)ri;
}

// ---------------- canonical serial-matvec pieces (128 thr, 1 bar/step) --------
__device__ __forceinline__ void load_row(float* ad, const float* __restrict__ M,
                                         int j) {
#pragma unroll
    for (int k = 0; k < NN; k++) ad[k] = M[k * NN + j];
}

__device__ __forceinline__ float dot128(const float* __restrict__ ad,
                                        const float* __restrict__ csh) {
    const float4* c4 = (const float4*)csh;
    float a0 = 0.f, a1 = 0.f, a2 = 0.f, a3 = 0.f;
#pragma unroll
    for (int k4 = 0; k4 < 32; k4++) {
        float4 cv = c4[k4];
        a0 = fmaf(ad[4 * k4 + 0], cv.x, a0);
        a1 = fmaf(ad[4 * k4 + 1], cv.y, a1);
        a2 = fmaf(ad[4 * k4 + 2], cv.z, a2);
        a3 = fmaf(ad[4 * k4 + 3], cv.w, a3);
    }
    return (a0 + a1) + (a2 + a3);
}

// ---------------- 3) chunk locals (256 blk) + P=Ad^16 columns (128 blk) -------
__global__ void __launch_bounds__(NN) k_chain(const float* __restrict__ f) {
    __shared__ float cur[2][NN];
    __shared__ float fsh[TC];
    int j = threadIdx.x;
    float ad[NN]; load_row(ad, g_AdT, j);

    int blk = blockIdx.x;
    if (blk < NB * KC) {                    // local scan from zero
        int b = blk >> 7, ch = blk & (KC - 1);
        float bd = g_Bd[j];
        if (j < TC) fsh[j] = f[b * LL + ch * TC + j];
        cur[0][j] = 0.f;
        __syncthreads();
        float nc = 0.f;
        for (int s = 0; s < TC; s++) {
            float d = dot128(ad, cur[s & 1]);
            nc = fmaf(bd, fsh[s], d);
            cur[(s + 1) & 1][j] = nc;
            __syncthreads();
        }
        g_locend[(b * KC + ch) * NN + j] = nc;
    } else {                                 // column j0 of P = Ad^16
        int j0 = blk - NB * KC;
        cur[0][j] = (j == j0) ? 1.f : 0.f;
        __syncthreads();
        float nc = 0.f;
        for (int s = 0; s < TC; s++) {
            nc = dot128(ad, cur[s & 1]);
            cur[(s + 1) & 1][j] = nc;
            __syncthreads();
        }
        g_PT[j0 * NN + j] = nc;              // P[j][j0]
    }
}

// ---------------- 4) Q=P^8 columns (128 blk) + group-local scans (32 blk) -----
__global__ void __launch_bounds__(NN) k_powgroup() {
    __shared__ float cur[2][NN];
    __shared__ float add[NG][NN];
    int j = threadIdx.x;
    float ap[NN]; load_row(ap, g_PT, j);

    int blk = blockIdx.x;
    if (blk < NN) {                          // column j0 of Q = P^8
        int j0 = blk;
        cur[0][j] = (j == j0) ? 1.f : 0.f;
        __syncthreads();
        float nc = 0.f;
        for (int s = 0; s < NG; s++) {
            nc = dot128(ap, cur[s & 1]);
            cur[(s + 1) & 1][j] = nc;
            __syncthreads();
        }
        g_QT[j0 * NN + j] = nc;
    } else {                                 // group-local: z <- P z + locend
        int gb = blk - NN;                   // 0..31
        int b = gb >> 4, g = gb & (GG - 1);
        for (int s = 0; s < NG; s++)
            add[s][j] = g_locend[(b * KC + g * NG + s) * NN + j];
        cur[0][j] = 0.f;
        __syncthreads();
        float nc = 0.f;
        for (int s = 0; s < NG; s++) {
            float d = dot128(ap, cur[s & 1]);
            nc = d + add[s][j];
            cur[(s + 1) & 1][j] = nc;
            __syncthreads();
        }
        g_gle[(b * GG + g) * NN + j] = nc;
    }
}

// ---------------- 5) fused carry: per-(b,g) Q-scan for group entry, then ------
// within-group P-chain for the 8 chunk carries. add columns are thread-private
// (thread j only touches add[*][j]); only cur is cross-thread.
__global__ void __launch_bounds__(NN) k_carryBC(float* __restrict__ cfin) {
    __shared__ float cur[2][NN];
    __shared__ float add[GG][NN];
    int j = threadIdx.x;
    int b = blockIdx.x >> 4, g = blockIdx.x & (GG - 1);

    float mrow[NN]; load_row(mrow, g_QT, j);

    int nload = (g == GG - 1) ? GG : g;     // gle[0..g-1] (+gle[15] for cfin)
    for (int s = 0; s < nload; s++)
        add[s][j] = g_gle[(b * GG + s) * NN + j];
    cur[0][j] = 0.f;
    __syncthreads();

    int buf = 0;
    for (int gg = 0; gg < g; gg++) {        // gentry(g) by Q-steps
        float d = dot128(mrow, cur[buf]);
        float nc = d + add[gg][j];
        buf ^= 1;
        cur[buf][j] = nc;
        __syncthreads();
    }
    if (g == GG - 1 && cfin != nullptr) {   // one extra Q-step -> c_final
        float d = dot128(mrow, cur[buf]);
        cfin[b * NN + j] = d + add[GG - 1][j];
    }

    // phase 2: within-group chunk carries with P
    load_row(mrow, g_PT, j);
    for (int s = 0; s < NG - 1; s++)        // add[*][j] thread-private
        add[s][j] = g_locend[(b * KC + g * NG + s) * NN + j];
    float e = cur[buf][j];
    g_carry[(b * KC + g * NG) * NN + j] = e;
    __syncthreads();                         // cfin/cur reads done before rewrite

    for (int c = 1; c < NG; c++) {
        float d = dot128(mrow, cur[buf]);
        float nc = d + add[c - 1][j];
        buf ^= 1;
        cur[buf][j] = nc;
        g_carry[(b * KC + g * NG + c) * NN + j] = nc;
        __syncthreads();
    }
}

// ---------------- 6) fused states+expand: recurrence into shared, then stream -
// grid (128, 2), 256 threads. Recurrence: half-split dot (h = tid>>7), 2 bars
// per step (R2-proven). Expand: 16 x 64KB coalesced float4 stores per block.
__global__ void __launch_bounds__(256) k_se(const float* __restrict__ f,
                                            const float* __restrict__ C,
                                            const float* __restrict__ D,
                                            float* __restrict__ y) {
    __shared__ float states[TC][NN];   // 8 KB
    __shared__ float cur[NN];
    __shared__ float part[NN];
    __shared__ float Csh[NN];
    __shared__ float fsh[TC];

    int tid = threadIdx.x;
    int ch = blockIdx.x, b = blockIdx.y;
    int j = tid & 127, h = tid >> 7;

    float ad[64];
#pragma unroll
    for (int k = 0; k < 64; k++) ad[k] = g_AdT[(h * 64 + k) * NN + j];
    float bd = (h == 0) ? g_Bd[j] : 0.f;

    if (tid < NN) {
        Csh[tid] = C[tid];
        cur[tid] = g_carry[(b * KC + ch) * NN + tid];
    }
    if (tid < TC) fsh[tid] = f[b * LL + ch * TC + tid];
    float Dv = D[0];
    __syncthreads();

    for (int s = 0; s < TC; s++) {
        const float4* c4 = (const float4*)cur + h * 16;
        float a0 = 0.f, a1 = 0.f, a2 = 0.f, a3 = 0.f;
#pragma unroll
        for (int k4 = 0; k4 < 16; k4++) {
            float4 cv = c4[k4];
            a0 = fmaf(ad[4 * k4 + 0], cv.x, a0);
            a1 = fmaf(ad[4 * k4 + 1], cv.y, a1);
            a2 = fmaf(ad[4 * k4 + 2], cv.z, a2);
            a3 = fmaf(ad[4 * k4 + 3], cv.w, a3);
        }
        float p = (a0 + a1) + (a2 + a3);
        if (h == 0) p = fmaf(bd, fsh[s], p);
        if (h == 1) part[j] = p;
        __syncthreads();                 // part ready; all cur reads done
        if (h == 0) {
            float nc = p + part[j];
            states[s][j] = nc;
            cur[j] = nc;
        }
        __syncthreads();
    }

    // stream: y[b,t,n,k] = C[n]*c_t[k] + D*f_t   (1 MB per block)
    size_t base = ((size_t)(b * LL + ch * TC)) * (NN * NN);
    for (int s = 0; s < TC; s++) {
        float df = Dv * fsh[s];
        float4* out = (float4*)(y + base + (size_t)s * (NN * NN));
        float4 cv = ((const float4*)states[s])[tid & 31];
        int n0 = tid >> 5;
#pragma unroll
        for (int it = 0; it < 16; it++) {
            float cn = Csh[n0 + 8 * it];
            float4 o;
            o.x = fmaf(cn, cv.x, df);
            o.y = fmaf(cn, cv.y, df);
            o.z = fmaf(cn, cv.z, df);
            o.w = fmaf(cn, cv.w, df);
            out[tid + 256 * it] = o;
        }
    }
}

// ---------------- launcher ----------------------------------------------------
extern "C" void kernel_launch(void* const* d_in, const int* in_sizes, int n_in,
                              void* d_out, int out_size) {
    const float* f = (const float*)d_in[0];
    const float* A = (const float*)d_in[1];
    const float* B = (const float*)d_in[2];
    const float* C = (const float*)d_in[3];
    const float* D = (const float*)d_in[4];

    const long long Y_ELEMS = (long long)NB * LL * NN * NN;   // 67,108,864
    long long off = (long long)out_size - Y_ELEMS;
    if (off < 0) off = 0;
    float* y    = (float*)d_out + off;
    float* cfin = (off >= NB * NN) ? (float*)d_out : nullptr;

    k_transpose<<<dim3(4, 4), dim3(32, 8)>>>(A);
    k_disc<<<NN + 1, NN>>>(B);
    k_chain<<<NB * KC + NN, NN>>>(f);        // 384 blocks
    k_powgroup<<<NN + NB * GG, NN>>>();      // 160 blocks
    k_carryBC<<<NB * GG, NN>>>(cfin);        // 32 blocks
    k_se<<<dim3(KC, NB), 256>>>(f, C, D, y);
}